// round 13
// baseline (speedup 1.0000x reference)
#include <cuda_runtime.h>

// TSModel 2-layer LSTM (layer0: 1->64; layer1: 64->1 fed c0; out = c1/step).
// B=2048 rows, T=1024 steps.
//
// R12 = R8 core + layer-1 merged into P2 (tail eliminated).
// 296 CTAs x 256 threads (2 CTAs/SM, 7 rows/CTA = balanced 14 rows/SM).
// P1 (unchanged): warp (q=wid>>1, kh=wid&1) computes gate-type q over K-half
//   kh for all 7 rows; lane l owns gate pair (64q+2l,+1); weights in 32 ull
//   regs; h via LDS.128 broadcast; partials -> gbuf.
// P2 (new): warp w (<7) owns row w; lane l owns units (2l, 2l+1). Combines
//   K-half partials, does the layer-0 cell update (c0 in regs), writes h,
//   and computes layer-1 IN-WARP: 4 packed FFMA2 partial dots over the just-
//   computed c values, a fold+butterfly shfl reduction, then the 1-wide
//   layer-1 recurrence replicated across lanes. No cbuf, no serial tail —
//   R8's ~300-cyc warp-0 appendix was on every step's critical path.

#define UNITS   64
#define TSTEPS  1024
#define ROWS    7
#define NCTA    296
#define NT      256
#define NROWS_TOTAL 2048

typedef unsigned long long ull;

__device__ __forceinline__ ull ffma2(ull a, ull b, ull c) {
    ull d;
    asm("fma.rn.f32x2 %0, %1, %2, %3;" : "=l"(d) : "l"(a), "l"(b), "l"(c));
    return d;
}
__device__ __forceinline__ ull addf2(ull a, ull b) {
    ull d;
    asm("add.rn.f32x2 %0, %1, %2;" : "=l"(d) : "l"(a), "l"(b));
    return d;
}
__device__ __forceinline__ ull pack2(float x, float y) {
    ull d;
    asm("mov.b64 %0, {%1, %2};" : "=l"(d) : "f"(x), "f"(y));
    return d;
}
__device__ __forceinline__ float2 unpack2(ull v) {
    float2 f;
    asm("mov.b64 {%0, %1}, %2;" : "=f"(f.x), "=f"(f.y) : "l"(v));
    return f;
}
__device__ __forceinline__ ull shfl64x(ull v, int m) {
    return __shfl_xor_sync(0xffffffffu, v, m);
}
__device__ __forceinline__ float sigf(float x) {
    return __fdividef(1.0f, 1.0f + __expf(-x));
}
__device__ __forceinline__ float tanhfast(float x) {
    return 2.0f * __fdividef(1.0f, 1.0f + __expf(-2.0f * x)) - 1.0f;
}

__global__ void __launch_bounds__(NT, 2)
lstm_kernel(const float* __restrict__ input,
            const float* __restrict__ W_ih0, const float* __restrict__ W_hh0,
            const float* __restrict__ b_ih0, const float* __restrict__ b_hh0,
            const float* __restrict__ W_ih1, const float* __restrict__ W_hh1,
            const float* __restrict__ b_ih1, const float* __restrict__ b_hh1,
            float* __restrict__ out)
{
    __shared__ __align__(16) float gbuf[ROWS][2][4][UNITS]; // K-half partials
    __shared__ __align__(16) float hbuf[ROWS][UNITS];       // h0 state
    __shared__ __align__(16) float xtile[ROWS][64];         // staged input

    const int row0 = blockIdx.x * ROWS;
    if (row0 >= NROWS_TOTAL) return;    // fully-OOB CTAs exit

    const int tid  = threadIdx.x;
    const int wid  = tid >> 5;
    const int lane = tid & 31;
    const int q    = wid >> 1;          // P1: gate type (i,f,g,o)
    const int kh   = wid & 1;           // P1: K-half

    // ---- one-time init ----
    const int gA = 64 * q + 2 * lane;   // lane's f32x2-adjacent gate pair
    const int gB = gA + 1;
    ull wregA[16], wregB[16];           // weights for K-slice [32kh,32kh+32)
    {
        const ulonglong2* wa = (const ulonglong2*)(W_hh0 + gA * UNITS + 32 * kh);
        const ulonglong2* wb = (const ulonglong2*)(W_hh0 + gB * UNITS + 32 * kh);
#pragma unroll
        for (int m = 0; m < 8; m++) {
            ulonglong2 va = wa[m], vb = wb[m];
            wregA[2 * m] = va.x; wregA[2 * m + 1] = va.y;
            wregB[2 * m] = vb.x; wregB[2 * m + 1] = vb.y;
        }
    }
    // x/bias injected only by the kh==0 warp (halves summed in P2)
    const float wihA = (kh == 0) ? W_ih0[gA] : 0.0f;
    const float wihB = (kh == 0) ? W_ih0[gB] : 0.0f;
    const float bsA  = (kh == 0) ? (b_ih0[gA] + b_hh0[gA]) : 0.0f;
    const float bsB  = (kh == 0) ? (b_ih0[gB] + b_hh0[gB]) : 0.0f;

    // P2/L1 constants: lane l owns units (2l, 2l+1) of row `wid`.
    ull w1q[4];                         // W_ih1[q][2l..2l+1] packed
    float wh1a[4], b1a[4];
#pragma unroll
    for (int k = 0; k < 4; k++) {
        w1q[k]  = pack2(W_ih1[k * UNITS + 2 * lane],
                        W_ih1[k * UNITS + 2 * lane + 1]);
        wh1a[k] = W_hh1[k];
        b1a[k]  = b_ih1[k] + b_hh1[k];
    }
    {
        float* hb = &hbuf[0][0];
        for (int i = tid; i < ROWS * UNITS; i += NT) hb[i] = 0.0f;
    }

    float2 c0s = make_float2(0.f, 0.f); // c0 for units (2l,2l+1) of row wid
    float  h1s = 0.f, c1s = 0.f;        // layer-1 state (replicated in warp)
    const bool p2w = (wid < ROWS);      // warp 7 has no P2 row

    __syncthreads();

    for (int t = 0; t < TSTEPS; t++) {
        const int tm = t & 63;
        if (tm == 0) {
            // stage 64 timesteps for the CTA's rows (coalesced; clamp OOB)
#pragma unroll
            for (int i = 0; i < 2; i++) {
                int lin = tid + NT * i;
                if (lin < ROWS * 64) {
                    int rr = lin >> 6, cc = lin & 63;
                    int grow = row0 + rr;
                    if (grow > NROWS_TOTAL - 1) grow = NROWS_TOTAL - 1;
                    xtile[rr][cc] = input[grow * TSTEPS + t + cc];
                }
            }
            __syncthreads();
        }

        // ---- P1: 2 gates x 7 rows over this K-half; 8 LDS.128 per row ----
#pragma unroll
        for (int r = 0; r < ROWS; r++) {
            const ulonglong2* hv = (const ulonglong2*)(hbuf[r] + 32 * kh);
            float xv = xtile[r][tm];
            ull accA = pack2(fmaf(xv, wihA, bsA), 0.0f);
            ull accB = pack2(fmaf(xv, wihB, bsB), 0.0f);
#pragma unroll
            for (int m = 0; m < 8; m++) {        // 8 x 16B = this K-half
                ulonglong2 h2 = hv[m];
                accA = ffma2(h2.x, wregA[2 * m],     accA);
                accB = ffma2(h2.x, wregB[2 * m],     accB);
                accA = ffma2(h2.y, wregA[2 * m + 1], accA);
                accB = ffma2(h2.y, wregB[2 * m + 1], accB);
            }
            float2 fa = unpack2(accA), fb = unpack2(accB);
            *(ull*)&gbuf[r][kh][q][2 * lane] = pack2(fa.x + fa.y, fb.x + fb.y);
        }
        __syncthreads();   // S1: partials ready

        // ---- P2 + layer 1: warp wid owns row wid (warps 0..6) ----
        if (p2w) {
            // combine K-halves for the lane's two units, all 4 gates (LDS.64)
            float2 si = unpack2(addf2(*(ull*)&gbuf[wid][0][0][2 * lane],
                                      *(ull*)&gbuf[wid][1][0][2 * lane]));
            float2 sf = unpack2(addf2(*(ull*)&gbuf[wid][0][1][2 * lane],
                                      *(ull*)&gbuf[wid][1][1][2 * lane]));
            float2 sg = unpack2(addf2(*(ull*)&gbuf[wid][0][2][2 * lane],
                                      *(ull*)&gbuf[wid][1][2][2 * lane]));
            float2 so = unpack2(addf2(*(ull*)&gbuf[wid][0][3][2 * lane],
                                      *(ull*)&gbuf[wid][1][3][2 * lane]));
            // layer-0 cell update for units 2l, 2l+1
            float ix = sigf(si.x),     iy = sigf(si.y);
            float fx = sigf(sf.x),     fy = sigf(sf.y);
            float gx = tanhfast(sg.x), gy = tanhfast(sg.y);
            float ox = sigf(so.x),     oy = sigf(so.y);
            float cnx = fmaf(fx, c0s.x, ix * gx);
            float cny = fmaf(fy, c0s.y, iy * gy);
            c0s.x = cnx; c0s.y = cny;
            *(ull*)&hbuf[wid][2 * lane] =
                pack2(ox * tanhfast(cnx), oy * tanhfast(cny));

            // layer-1 partial dots over the CELL state (ref quirk): lane's
            // 2-unit contribution to all 4 gates, packed.
            ull cpk = pack2(cnx, cny);
            float p[4];
#pragma unroll
            for (int k = 0; k < 4; k++) {
                float2 pp = unpack2(ffma2(cpk, w1q[k], 0ULL));
                p[k] = pp.x + pp.y;
            }
            // fold (p0,p1)/(p2,p3) then butterfly across the warp
            ull q01 = pack2(p[0], p[1]);
            ull q23 = pack2(p[2], p[3]);
            ull o01 = shfl64x(q01, 1);
            ull o23 = shfl64x(q23, 1);
            ull s = (lane & 1) ? addf2(q23, o23) : addf2(q01, o01);
            s = addf2(s, shfl64x(s, 2));
            s = addf2(s, shfl64x(s, 4));
            s = addf2(s, shfl64x(s, 8));
            s = addf2(s, shfl64x(s, 16));
            ull o = shfl64x(s, 1);
            float2 s2 = unpack2(s), o2 = unpack2(o);
            float P0 = (lane & 1) ? o2.x : s2.x;
            float P1 = (lane & 1) ? o2.y : s2.y;
            float P2 = (lane & 1) ? s2.x : o2.x;
            float P3 = (lane & 1) ? s2.y : o2.y;

            // layer-1 recurrence (replicated identically in all 32 lanes)
            float i1 = sigf(fmaf(wh1a[0], h1s, P0 + b1a[0]));
            float f1 = sigf(fmaf(wh1a[1], h1s, P1 + b1a[1]));
            float g1 = tanhfast(fmaf(wh1a[2], h1s, P2 + b1a[2]));
            float o1 = sigf(fmaf(wh1a[3], h1s, P3 + b1a[3]));
            float c1n = fmaf(f1, c1s, i1 * g1);
            c1s = c1n;
            h1s = o1 * tanhfast(c1n);
            if (lane == 0 && (row0 + wid) < NROWS_TOTAL)
                out[(row0 + wid) * TSTEPS + t] = c1n;
        }
        __syncthreads();   // S2: h ready for next P1
    }
}

extern "C" void kernel_launch(void* const* d_in, const int* in_sizes, int n_in,
                              void* d_out, int out_size) {
    const float* input = (const float*)d_in[0];
    const float* W_ih0 = (const float*)d_in[1];
    const float* W_hh0 = (const float*)d_in[2];
    const float* b_ih0 = (const float*)d_in[3];
    const float* b_hh0 = (const float*)d_in[4];
    const float* W_ih1 = (const float*)d_in[5];
    const float* W_hh1 = (const float*)d_in[6];
    const float* b_ih1 = (const float*)d_in[7];
    const float* b_hh1 = (const float*)d_in[8];
    float* out = (float*)d_out;

    lstm_kernel<<<NCTA, NT>>>(
        input, W_ih0, W_hh0, b_ih0, b_hh0, W_ih1, W_hh1, b_ih1, b_hh1, out);
}

// round 14
// speedup vs baseline: 1.1377x; 1.1377x over previous
#include <cuda_runtime.h>

// TSModel 2-layer LSTM (layer0: 1->64; layer1: 64->1 fed c0; out = c1/step).
// B=2048 rows, T=1024 steps.
//
// R13 = R8 (best passing: 2073us) with ONE change: activations built on
// MUFU.TANH (tanh.approx.f32) instead of EX2+RCP chains.
//   tanh(x):    1 MUFU (lat 16)            [was ~40+ cyc chain]
//   sigmoid(x): FMUL + MUFU.TANH + FFMA    [was ~40+ cyc chain]
// This shortens the barrier-bounded P2 serial window (four sigmoids + two
// tanh per thread in sequence) and the warp-0 layer-1 tail — the ~1650
// cyc/step of non-FMA critical path that R11/R12 structural changes failed
// to dent. Error budget: MUFU.TANH abs err ~5e-4, contractive recurrence;
// predicted rel_err ~1e-5..1e-4 vs 1e-3 threshold.
//
// R8 recap: 296 CTAs x 256 threads (2 CTAs/SM, 7 rows/CTA = 14 rows/SM).
// Warp (q=wid>>1, kh=wid&1): gate-type q, K-half kh; lane l owns gate pair
// (64q+2l,+1) with K-slice weights in 32 ull regs; h via LDS.128 broadcast.
// P1 -> gbuf | bar | P2 cell update | bar | layer-1 tail on warp 0.

#define UNITS   64
#define TSTEPS  1024
#define ROWS    7
#define NCTA    296
#define NT      256
#define NROWS_TOTAL 2048

typedef unsigned long long ull;

__device__ __forceinline__ ull ffma2(ull a, ull b, ull c) {
    ull d;
    asm("fma.rn.f32x2 %0, %1, %2, %3;" : "=l"(d) : "l"(a), "l"(b), "l"(c));
    return d;
}
__device__ __forceinline__ ull pack2(float x, float y) {
    ull d;
    asm("mov.b64 %0, {%1, %2};" : "=l"(d) : "f"(x), "f"(y));
    return d;
}
__device__ __forceinline__ float2 unpack2(ull v) {
    float2 f;
    asm("mov.b64 {%0, %1}, %2;" : "=f"(f.x), "=f"(f.y) : "l"(v));
    return f;
}
__device__ __forceinline__ float tanhapx(float x) {
    float y;
    asm("tanh.approx.f32 %0, %1;" : "=f"(y) : "f"(x));
    return y;
}
__device__ __forceinline__ float sigf(float x) {
    return fmaf(0.5f, tanhapx(0.5f * x), 0.5f);
}
__device__ __forceinline__ float tanhfast(float x) {
    return tanhapx(x);
}

__global__ void __launch_bounds__(NT, 2)
lstm_kernel(const float* __restrict__ input,
            const float* __restrict__ W_ih0, const float* __restrict__ W_hh0,
            const float* __restrict__ b_ih0, const float* __restrict__ b_hh0,
            const float* __restrict__ W_ih1, const float* __restrict__ W_hh1,
            const float* __restrict__ b_ih1, const float* __restrict__ b_hh1,
            float* __restrict__ out)
{
    __shared__ __align__(16) float gbuf[ROWS][2][4][UNITS]; // K-half partials
    __shared__ __align__(16) float hbuf[ROWS][UNITS];       // h0 state
    __shared__ __align__(16) float cbuf[ROWS][68];          // c0_new (padded)
    __shared__ __align__(16) float xtile[ROWS][64];         // staged input
    __shared__ __align__(16) float W1s[4][68];              // W_ih1

    const int row0 = blockIdx.x * ROWS;
    if (row0 >= NROWS_TOTAL) return;    // fully-OOB CTAs exit

    const int tid  = threadIdx.x;
    const int wid  = tid >> 5;
    const int lane = tid & 31;
    const int q    = wid >> 1;          // gate type (i,f,g,o)
    const int kh   = wid & 1;           // K-half

    // ---- one-time init ----
    const int gA = 64 * q + 2 * lane;   // lane's f32x2-adjacent gate pair
    const int gB = gA + 1;
    ull wregA[16], wregB[16];           // weights for K-slice [32kh,32kh+32)
    {
        const ulonglong2* wa = (const ulonglong2*)(W_hh0 + gA * UNITS + 32 * kh);
        const ulonglong2* wb = (const ulonglong2*)(W_hh0 + gB * UNITS + 32 * kh);
#pragma unroll
        for (int m = 0; m < 8; m++) {
            ulonglong2 va = wa[m], vb = wb[m];
            wregA[2 * m] = va.x; wregA[2 * m + 1] = va.y;
            wregB[2 * m] = vb.x; wregB[2 * m + 1] = vb.y;
        }
    }
    // x/bias injected only by the kh==0 warp (halves summed in P2)
    const float wihA = (kh == 0) ? W_ih0[gA] : 0.0f;
    const float wihB = (kh == 0) ? W_ih0[gB] : 0.0f;
    const float bsA  = (kh == 0) ? (b_ih0[gA] + b_hh0[gA]) : 0.0f;
    const float bsB  = (kh == 0) ? (b_ih0[gB] + b_hh0[gB]) : 0.0f;

    float wh1a[4], b1a[4];
#pragma unroll
    for (int k = 0; k < 4; k++) { wh1a[k] = W_hh1[k]; b1a[k] = b_ih1[k] + b_hh1[k]; }
    if (tid < 4 * UNITS) W1s[tid >> 6][tid & 63] = W_ih1[tid];
    {
        float* hb = &hbuf[0][0];
        for (int i = tid; i < ROWS * UNITS; i += NT) hb[i] = 0.0f;
    }

    // P2 identity: unit u2, rows {rs, rs+4} (second row only for rs<3)
    const int u2 = tid & 63;
    const int rs = tid >> 6;            // 0..3
    float c0s[2] = {0.f, 0.f};

    // layer-1 identity (warp 0): row r1 (0..7, clamp), gate q1
    const int r1 = tid >> 2, q1 = tid & 3;
    const int r1c = (r1 < ROWS) ? r1 : (ROWS - 1);
    float h1s = 0.f, c1s = 0.f;

    __syncthreads();

    for (int t = 0; t < TSTEPS; t++) {
        const int tm = t & 63;
        if (tm == 0) {
            // stage 64 timesteps for the CTA's rows (coalesced; clamp OOB)
#pragma unroll
            for (int i = 0; i < 2; i++) {
                int lin = tid + NT * i;
                if (lin < ROWS * 64) {
                    int rr = lin >> 6, cc = lin & 63;
                    int grow = row0 + rr;
                    if (grow > NROWS_TOTAL - 1) grow = NROWS_TOTAL - 1;
                    xtile[rr][cc] = input[grow * TSTEPS + t + cc];
                }
            }
            __syncthreads();
        }

        // ---- P1: 2 gates x 7 rows over this K-half; 8 LDS.128 per row ----
#pragma unroll
        for (int r = 0; r < ROWS; r++) {
            const ulonglong2* hv = (const ulonglong2*)(hbuf[r] + 32 * kh);
            float xv = xtile[r][tm];
            ull accA = pack2(fmaf(xv, wihA, bsA), 0.0f);
            ull accB = pack2(fmaf(xv, wihB, bsB), 0.0f);
#pragma unroll
            for (int m = 0; m < 8; m++) {        // 8 x 16B = this K-half
                ulonglong2 h2 = hv[m];
                accA = ffma2(h2.x, wregA[2 * m],     accA);
                accB = ffma2(h2.x, wregB[2 * m],     accB);
                accA = ffma2(h2.y, wregA[2 * m + 1], accA);
                accB = ffma2(h2.y, wregB[2 * m + 1], accB);
            }
            float2 fa = unpack2(accA), fb = unpack2(accB);
            *(ull*)&gbuf[r][kh][q][2 * lane] = pack2(fa.x + fa.y, fb.x + fb.y);
        }
        __syncthreads();   // S1: partials ready

        // ---- P2: combine K-halves + layer-0 cell update ----
#pragma unroll
        for (int j = 0; j < 2; j++) {
            const int r = rs + 4 * j;
            if (j == 1 && rs >= ROWS - 4) break;   // rows 4..6 only
            float iv = sigf(gbuf[r][0][0][u2] + gbuf[r][1][0][u2]);
            float fv = sigf(gbuf[r][0][1][u2] + gbuf[r][1][1][u2]);
            float gv = tanhfast(gbuf[r][0][2][u2] + gbuf[r][1][2][u2]);
            float ov = sigf(gbuf[r][0][3][u2] + gbuf[r][1][3][u2]);
            float c  = fmaf(fv, c0s[j], iv * gv);
            c0s[j] = c;
            hbuf[r][u2] = ov * tanhfast(c);
            cbuf[r][u2] = c;   // layer-1 input is the CELL state (ref quirk)
        }
        __syncthreads();   // S2: h, c0_new ready

        // ---- layer 1 (warp 0 only); other warps run ahead to next P1 ----
        if (tid < 32) {
            const ulonglong2* cv = (const ulonglong2*)cbuf[r1c];
            const ulonglong2* wv = (const ulonglong2*)W1s[q1];
            ull pa = 0ULL, pb = 0ULL;
#pragma unroll
            for (int m = 0; m < 16; m++) {       // full 64-element dot
                ulonglong2 c2 = cv[m], w2 = wv[m];
                pa = ffma2(c2.x, w2.x, pa);
                pb = ffma2(c2.y, w2.y, pb);
            }
            float2 fa = unpack2(pa), fb = unpack2(pb);
            float pre = (fa.x + fb.x) + (fa.y + fb.y)
                      + b1a[q1] + wh1a[q1] * h1s;
            float act = (q1 == 2) ? tanhfast(pre) : sigf(pre);

            // gather the 4 gate values within each 4-lane row group
            float a1 = __shfl_xor_sync(0xffffffffu, act, 1);
            float gAv = (q1 & 1) ? a1 : act;    // gate[q & ~1]
            float gBv = (q1 & 1) ? act : a1;    // gate[q | 1]
            float cA = __shfl_xor_sync(0xffffffffu, gAv, 2);
            float cB = __shfl_xor_sync(0xffffffffu, gBv, 2);
            float i1, f1, g1v, o1v;
            if (q1 < 2) { i1 = gAv; f1 = gBv; g1v = cA; o1v = cB; }
            else        { i1 = cA;  f1 = cB;  g1v = gAv; o1v = gBv; }

            float c1n = fmaf(f1, c1s, i1 * g1v);
            c1s = c1n;
            h1s = o1v * tanhfast(c1n);
            if (q1 == 0 && r1 < ROWS && (row0 + r1) < NROWS_TOTAL)
                out[(row0 + r1) * TSTEPS + t] = c1n;
        }
    }
}

extern "C" void kernel_launch(void* const* d_in, const int* in_sizes, int n_in,
                              void* d_out, int out_size) {
    const float* input = (const float*)d_in[0];
    const float* W_ih0 = (const float*)d_in[1];
    const float* W_hh0 = (const float*)d_in[2];
    const float* b_ih0 = (const float*)d_in[3];
    const float* b_hh0 = (const float*)d_in[4];
    const float* W_ih1 = (const float*)d_in[5];
    const float* W_hh1 = (const float*)d_in[6];
    const float* b_ih1 = (const float*)d_in[7];
    const float* b_hh1 = (const float*)d_in[8];
    float* out = (float*)d_out;

    lstm_kernel<<<NCTA, NT>>>(
        input, W_ih0, W_hh0, b_ih0, b_hh0, W_ih1, W_hh1, b_ih1, b_hh1, out);
}